// round 8
// baseline (speedup 1.0000x reference)
#include <cuda_runtime.h>
#include <cuda_bf16.h>
#include <math.h>
#include <stdint.h>

#define BSZ 2048
#define HS  512
#define RS  64
#define MS  128
#define CAT0 832
#define XCU 896
#define GN  1536
#define OC  576

typedef __nv_bfloat16 bf16;

// ---------------- scratch (device globals; no allocations) ----------------
__device__ __align__(16) float g_base [BSZ*128];
__device__ __align__(16) float g_keyW [128*128];
__device__ __align__(16) float g_ab   [BSZ*2];
__device__             int   g_idx  [BSZ];
__device__ __align__(16) float g_r    [BSZ*RS];
__device__ __align__(16) float g_G    [BSZ*GN];
__device__ __align__(16) float g_P    [BSZ*HS];
__device__ __align__(16) float g_veca [128];
__device__ __align__(16) float g_uinv [BSZ];
__device__ __align__(16) bf16 g_WG_hi[GN*CAT0],  g_WG_lo[GN*CAT0];
__device__ __align__(16) bf16 g_WP_hi[HS*CAT0],  g_WP_lo[HS*CAT0];
__device__ __align__(16) bf16 g_Wb_hi[128*XCU];
__device__ __align__(16) bf16 g_Ww_hi[64*768],   g_Ww_lo[64*768];
__device__ __align__(16) bf16 g_Wm_hi[128*64];

__device__ __forceinline__ float tanh_fast(float x) {
    float y; asm("tanh.approx.f32 %0, %1;" : "=f"(y) : "f"(x)); return y;
}
__device__ __forceinline__ float sigm(float x) { return 1.f/(1.f+expf(-x)); }
__device__ __forceinline__ float gumbel(float u) {
    return -logf(1e-20f - logf(1e-20f + u));
}
__device__ __forceinline__ void split2(float a, float b, uint32_t& hi, uint32_t& lo) {
    __nv_bfloat162 h, l;
    h.x = __float2bfloat16(a); h.y = __float2bfloat16(b);
    l.x = __float2bfloat16(a - __bfloat162float(h.x));
    l.y = __float2bfloat16(b - __bfloat162float(h.y));
    hi = *(uint32_t*)&h; lo = *(uint32_t*)&l;
}
__device__ __forceinline__ uint32_t pack_hi2(float a, float b) {
    __nv_bfloat162 h; h.x = __float2bfloat16(a); h.y = __float2bfloat16(b);
    return *(uint32_t*)&h;
}
__device__ __forceinline__ void mma_bf16(float* c, const uint32_t* a, uint32_t b0, uint32_t b1) {
    asm volatile("mma.sync.aligned.m16n8k16.row.col.f32.bf16.bf16.f32 "
        "{%0,%1,%2,%3},{%4,%5,%6,%7},{%8,%9},{%0,%1,%2,%3};"
        : "+f"(c[0]), "+f"(c[1]), "+f"(c[2]), "+f"(c[3])
        : "r"(a[0]), "r"(a[1]), "r"(a[2]), "r"(a[3]), "r"(b0), "r"(b1));
}
#define LDSM_X4(r, addr) \
    asm volatile("ldmatrix.sync.aligned.m8n8.x4.shared.b16 {%0,%1,%2,%3}, [%4];" \
        : "=r"((r)[0]), "=r"((r)[1]), "=r"((r)[2]), "=r"((r)[3]) : "r"(addr))
#define CP_ASYNC16(saddr, gptr) \
    asm volatile("cp.async.cg.shared.global [%0], [%1], 16;" :: "r"(saddr), "l"(gptr))
#define CP_COMMIT() asm volatile("cp.async.commit_group;" ::: "memory")
#define CP_WAIT0()  asm volatile("cp.async.wait_group 0;" ::: "memory")
__device__ __forceinline__ uint32_t sptr(const void* p) {
    return (uint32_t)__cvta_generic_to_shared(p);
}

// ---------------- k_prep ----------------
__device__ void tsplit_tile(const float* __restrict__ src, bf16* __restrict__ dhi,
                            bf16* __restrict__ dlo, int K, int N, int split, int extra,
                            int tile, int tid) {
    __shared__ float t[32][33];
    int nt = N/32;
    int n0 = (tile % nt)*32, k0 = (tile / nt)*32;
    int tx = tid & 31, ty = tid >> 5;
    for (int r = ty; r < 32; r += 8) {
        int k = k0 + r; int sr = (k < split) ? k : k + extra;
        t[r][tx] = src[(size_t)sr*N + n0 + tx];
    }
    __syncthreads();
    for (int r = ty; r < 32; r += 8) {
        float v = t[tx][r];
        bf16 hi = __float2bfloat16(v);
        size_t o = (size_t)(n0 + r)*K + k0 + tx;
        dhi[o] = hi;
        if (dlo) dlo[o] = __float2bfloat16(v - __bfloat162float(hi));
    }
}

#define T_WG 1248
#define T_WP (T_WG + 416)
#define T_WB (T_WP + 112)
#define T_WW (T_WB + 48)
#define T_WM (T_WW + 8)
#define T_KW (T_WM + 64)
#define T_UN (T_KW + 256)
#define T_ALL (T_UN + 1)

__global__ __launch_bounds__(256) void k_prep(
    const float* __restrict__ W_full, const float* __restrict__ W_full2,
    const float* __restrict__ W_fc,   const float* __restrict__ W_fc1,
    const float* __restrict__ keys,   const float* __restrict__ vec_a,
    const float* __restrict__ u) {
    int blk = blockIdx.x, tid = threadIdx.x;
    if (blk < T_WG) {
        tsplit_tile(W_full, g_WG_hi, g_WG_lo, CAT0, GN, CAT0, 0, blk, tid);
    } else if (blk < T_WP) {
        tsplit_tile(W_full2, g_WP_hi, g_WP_lo, CAT0, HS, CAT0, 0, blk - T_WG, tid);
    } else if (blk < T_WB) {
        tsplit_tile(W_fc, g_Wb_hi, nullptr, XCU, 128, 768, 128, blk - T_WP, tid);
    } else if (blk < T_WW) {
        tsplit_tile(W_fc1, g_Ww_hi, g_Ww_lo, 768, 64, 768, 0, blk - T_WB, tid);
    } else if (blk < T_WM) {
        tsplit_tile(W_fc + 832*128, g_Wm_hi, nullptr, 64, 128, 64, 0, blk - T_WW, tid);
    } else if (blk < T_KW) {
        __shared__ float krow[2][64];
        int sub = tid >> 7, t = tid & 127;
        int m = (blk - T_WM)*2 + sub;
        if (t < 64) krow[sub][t] = keys[m*64 + t];
        __syncthreads();
        float acc = 0.f;
        #pragma unroll 8
        for (int r = 0; r < 64; r++) acc += krow[sub][r] * W_fc[(768+r)*128 + t];
        g_keyW[m*128 + t] = acc;
    } else if (blk < T_UN) {
        int w = tid >> 5, lane = tid & 31;
        int b = (blk - T_KW)*8 + w;
        float s = 0.f;
        #pragma unroll
        for (int j = lane; j < 128; j += 32) { float v = u[b*128+j]; s += v*v; }
        #pragma unroll
        for (int o = 16; o > 0; o >>= 1) s += __shfl_down_sync(0xffffffffu, s, o);
        if (lane == 0) g_uinv[b] = 1.f / fmaxf(sqrtf(s), 1e-12f);
    } else {
        if (tid < 128) g_veca[tid] = vec_a[tid];
    }
}

// ---------------- k_gp: merged G+P GEMM + interleaved hmem copy ----------------
#define GP_NGX 24
#define GP_SMEM 61440
__global__ __launch_bounds__(256, 2) void k_gp(
    const float* __restrict__ x, const float* __restrict__ h,
    const float* __restrict__ biasG, const float* __restrict__ bias2,
    const float* __restrict__ hmem, float* __restrict__ out_hmem) {
    constexpr int BK = 32, LDA = 40;
    constexpr int BM = 128, BN = 64;
    constexpr int ASZ = BM*LDA, BSZE = BN*LDA;
    constexpr int STAGE = (ASZ + BSZE) * 2;
    constexpr int MF = 2, NF = 4;
    extern __shared__ __align__(16) bf16 sm[];
    int tid = threadIdx.x;
    int w = tid >> 5, lane = tid & 31, g = lane >> 2, tg = lane & 3;
    int wm = w >> 1, wn = w & 1;
    bool isP = blockIdx.x >= GP_NGX;
    int n0 = (isP ? (int)blockIdx.x - GP_NGX : (int)blockIdx.x) * BN;
    int m0 = blockIdx.y * BM;
    const bf16* BT_hi = isP ? g_WP_hi : g_WG_hi;
    const bf16* BT_lo = isP ? g_WP_lo : g_WG_lo;
    const int KT = CAT0 / BK;   // 26
    float c[MF][NF][4] = {};

    // distributed hmem copy: 8192 float4 per block, 512 per k-iteration (16 iters)
    size_t cbase = ((size_t)(blockIdx.y * gridDim.x + blockIdx.x)) * 8192;
    const float4* csrc = (const float4*)hmem;
    float4* cdst = (float4*)out_hmem;
    float4 cb0, cb1;

    uint32_t a_off = (uint32_t)(((((lane>>3)&1)*8 + (lane&7))*LDA + (lane>>4)*8) * 2);
    uint32_t b_off = (uint32_t)((((lane&7) + ((lane>>4)&1)*8)*LDA + ((lane>>3)&1)*8) * 2);

    // A tile: 128 rows x 32 cols. Each thread: 2 pair-loads of 8 floats from one row.
    float4 av0[2], av1[2];
    auto ldA = [&](int kt) {
        #pragma unroll
        for (int l = 0; l < 2; l++) {
            int i = tid + l*256;
            int row = i >> 2, p = i & 3;
            int gr = m0 + row, kk = kt*BK + p*8;
            float4 v0, v1;
            if (kk < 256) {
                v0 = *(const float4*)&x[(size_t)gr*256 + kk];
                v1 = *(const float4*)&x[(size_t)gr*256 + kk + 4];
            } else if (kk < 768) {
                v0 = *(const float4*)&h[(size_t)gr*512 + kk-256];
                v1 = *(const float4*)&h[(size_t)gr*512 + kk-252];
            } else {
                v0 = *(const float4*)&g_r[(size_t)gr*64 + kk-768];
                v1 = *(const float4*)&g_r[(size_t)gr*64 + kk-764];
            }
            if (isP) {
                float s = (kk >= 768) ? g_ab[gr*2+1] : (kk >= 256) ? g_ab[gr*2] : 1.f;
                v0.x *= s; v0.y *= s; v0.z *= s; v0.w *= s;
                v1.x *= s; v1.y *= s; v1.z *= s; v1.w *= s;
            }
            av0[l] = v0; av1[l] = v1;
        }
    };
    auto stA = [&](int s) {
        bf16* Ah = sm + s*STAGE;
        bf16* Al = Ah + ASZ;
        #pragma unroll
        for (int l = 0; l < 2; l++) {
            int i = tid + l*256;
            int row = i >> 2, p = i & 3;
            float4 v0 = av0[l], v1 = av1[l];
            uint4 hi, lo;
            split2(v0.x, v0.y, hi.x, lo.x);
            split2(v0.z, v0.w, hi.y, lo.y);
            split2(v1.x, v1.y, hi.z, lo.z);
            split2(v1.z, v1.w, hi.w, lo.w);
            *(uint4*)&Ah[row*LDA + p*8] = hi;
            *(uint4*)&Al[row*LDA + p*8] = lo;
        }
    };
    auto ldB = [&](int s, int kt) {
        bf16* Bh = sm + s*STAGE + ASZ*2;
        bf16* Bl = Bh + BSZE;
        int r = tid >> 2, q = tid & 3;
        CP_ASYNC16(sptr(&Bh[r*LDA + q*8]), &BT_hi[(size_t)(n0+r)*CAT0 + kt*BK + q*8]);
        CP_ASYNC16(sptr(&Bl[r*LDA + q*8]), &BT_lo[(size_t)(n0+r)*CAT0 + kt*BK + q*8]);
    };

    ldA(0); ldB(0, 0); CP_COMMIT(); stA(0);
    cb0 = csrc[cbase + tid];
    cb1 = csrc[cbase + 256 + tid];
    CP_WAIT0(); __syncthreads();

    for (int kt = 0; kt < KT; kt++) {
        int s = kt & 1;
        bool nxt = (kt + 1 < KT);
        if (nxt) { ldB(s^1, kt+1); CP_COMMIT(); ldA(kt+1); }
        if (kt < 16) {
            size_t o = cbase + (size_t)kt*512 + tid;
            cdst[o] = cb0;
            cdst[o + 256] = cb1;
            if (kt + 1 < 16) {
                size_t o2 = o + 512;
                cb0 = csrc[o2];
                cb1 = csrc[o2 + 256];
            }
        }

        uint32_t ahb = sptr(sm + s*STAGE) + (uint32_t)(wm*MF*16*LDA*2) + a_off;
        uint32_t alb = ahb + (uint32_t)(ASZ*2);
        uint32_t bhb = sptr(sm + s*STAGE + ASZ*2) + (uint32_t)(wn*NF*8*LDA*2) + b_off;
        uint32_t blb = bhb + (uint32_t)(BSZE*2);
        #pragma unroll
        for (int k0 = 0; k0 < BK; k0 += 16) {
            uint32_t ah[MF][4], al[MF][4];
            #pragma unroll
            for (int mf = 0; mf < MF; mf++) {
                LDSM_X4(ah[mf], ahb + (uint32_t)((mf*16*LDA + k0)*2));
                LDSM_X4(al[mf], alb + (uint32_t)((mf*16*LDA + k0)*2));
            }
            #pragma unroll
            for (int np = 0; np < NF/2; np++) {
                uint32_t bh[4], bl[4];
                LDSM_X4(bh, bhb + (uint32_t)((np*16*LDA + k0)*2));
                LDSM_X4(bl, blb + (uint32_t)((np*16*LDA + k0)*2));
                #pragma unroll
                for (int mf = 0; mf < MF; mf++) {
                    mma_bf16(c[mf][2*np],   ah[mf], bh[0], bh[1]);
                    mma_bf16(c[mf][2*np+1], ah[mf], bh[2], bh[3]);
                    mma_bf16(c[mf][2*np],   al[mf], bh[0], bh[1]);
                    mma_bf16(c[mf][2*np+1], al[mf], bh[2], bh[3]);
                    mma_bf16(c[mf][2*np],   ah[mf], bl[0], bl[1]);
                    mma_bf16(c[mf][2*np+1], ah[mf], bl[2], bl[3]);
                }
            }
        }
        if (nxt) stA(s^1);
        CP_WAIT0(); __syncthreads();
    }

    float* C = isP ? g_P : g_G;
    const float* bias = isP ? bias2 : biasG;
    int N = isP ? HS : GN;
    #pragma unroll
    for (int mf = 0; mf < MF; mf++) {
        int r0 = m0 + wm*MF*16 + mf*16 + g;
        #pragma unroll
        for (int nf = 0; nf < NF; nf++) {
            int cb = n0 + wn*NF*8 + nf*8 + 2*tg;
            C[(size_t)r0*N + cb]       = c[mf][nf][0] + bias[cb];
            C[(size_t)r0*N + cb + 1]   = c[mf][nf][1] + bias[cb+1];
            C[(size_t)(r0+8)*N + cb]   = c[mf][nf][2] + bias[cb];
            C[(size_t)(r0+8)*N + cb+1] = c[mf][nf][3] + bias[cb+1];
        }
    }
}

// ---------------- generic pipelined GEMM (base) ----------------
template<int WM, int WN, int MF, int NF>
__global__ __launch_bounds__(WM*WN*32) void mgemm_base(
    const float* __restrict__ p0, const float* __restrict__ p1,
    const float* __restrict__ p2, const float* __restrict__ aux,
    const bf16* __restrict__ BT_hi,
    float* __restrict__ C, const float* __restrict__ bias, int N, int K) {
    constexpr int BK = 32, LDA = 40;
    constexpr int BM = WM*MF*16, BN = WN*NF*8, NT = WM*WN*32;
    constexpr int ASZ = BM*LDA, BSZE = BN*LDA;
    constexpr int STAGE = ASZ + BSZE;
    constexpr int ALOADS = BM*BK/4/NT;
    constexpr int BCHUNK = BN*BK/8/NT;
    extern __shared__ __align__(16) bf16 sm[];
    int tid = threadIdx.x;
    int w = tid >> 5, lane = tid & 31, g = lane >> 2, tg = lane & 3;
    int wm = w / WN, wn = w % WN;
    int m0 = blockIdx.y*BM, n0 = blockIdx.x*BN;
    const int KT = K / BK;
    float c[MF][NF][4] = {};

    uint32_t a_off = (uint32_t)(((((lane>>3)&1)*8 + (lane&7))*LDA + (lane>>4)*8) * 2);
    uint32_t b_off = (uint32_t)((((lane&7) + ((lane>>4)&1)*8)*LDA + ((lane>>3)&1)*8) * 2);

    float4 av[ALOADS];
    auto ldA = [&](int kt) {
        #pragma unroll
        for (int l = 0; l < ALOADS; l++) {
            int i = tid + l*NT;
            int row = i/(BK/4), q = i%(BK/4);
            int gr = m0 + row, kk = kt*BK + q*4;
            float4 v;
            if (kk < 256)      v = *(const float4*)&p0[(size_t)gr*256 + kk];
            else if (kk < 768) v = *(const float4*)&p1[(size_t)gr*512 + kk-256];
            else {
                v = *(const float4*)&p2[(size_t)gr*128 + kk-768];
                float s = aux[gr];
                v.x *= s; v.y *= s; v.z *= s; v.w *= s;
            }
            av[l] = v;
        }
    };
    auto stA = [&](int s) {
        bf16* Ah = sm + s*STAGE;
        #pragma unroll
        for (int l = 0; l < ALOADS; l++) {
            int i = tid + l*NT;
            int row = i/(BK/4), q = i%(BK/4);
            float4 v = av[l];
            uint2 hh; hh.x = pack_hi2(v.x, v.y); hh.y = pack_hi2(v.z, v.w);
            *(uint2*)&Ah[row*LDA + q*4] = hh;
        }
    };
    auto ldB = [&](int s, int kt) {
        bf16* Bh = sm + s*STAGE + ASZ;
        #pragma unroll
        for (int l = 0; l < BCHUNK; l++) {
            int i = tid + l*NT;
            int r = i/(BK/8), q = i%(BK/8);
            CP_ASYNC16(sptr(&Bh[r*LDA + q*8]), &BT_hi[(size_t)(n0+r)*K + kt*BK + q*8]);
        }
    };

    ldA(0); ldB(0, 0); CP_COMMIT(); stA(0);
    CP_WAIT0(); __syncthreads();

    for (int kt = 0; kt < KT; kt++) {
        int s = kt & 1;
        bool nxt = (kt + 1 < KT);
        if (nxt) { ldB(s^1, kt+1); CP_COMMIT(); ldA(kt+1); }

        uint32_t ahb = sptr(sm + s*STAGE) + (uint32_t)(wm*MF*16*LDA*2) + a_off;
        uint32_t bhb = sptr(sm + s*STAGE + ASZ) + (uint32_t)(wn*NF*8*LDA*2) + b_off;
        #pragma unroll
        for (int k0 = 0; k0 < BK; k0 += 16) {
            uint32_t ah[MF][4];
            #pragma unroll
            for (int mf = 0; mf < MF; mf++)
                LDSM_X4(ah[mf], ahb + (uint32_t)((mf*16*LDA + k0)*2));
            #pragma unroll
            for (int np = 0; np < NF/2; np++) {
                uint32_t bh[4];
                LDSM_X4(bh, bhb + (uint32_t)((np*16*LDA + k0)*2));
                #pragma unroll
                for (int mf = 0; mf < MF; mf++) {
                    mma_bf16(c[mf][2*np],   ah[mf], bh[0], bh[1]);
                    mma_bf16(c[mf][2*np+1], ah[mf], bh[2], bh[3]);
                }
            }
        }
        if (nxt) stA(s^1);
        CP_WAIT0(); __syncthreads();
    }

    #pragma unroll
    for (int mf = 0; mf < MF; mf++) {
        int r0 = m0 + wm*MF*16 + mf*16 + g;
        #pragma unroll
        for (int nf = 0; nf < NF; nf++) {
            int cb = n0 + wn*NF*8 + nf*8 + 2*tg;
            C[(size_t)r0*N + cb]       = c[mf][nf][0] + bias[cb];
            C[(size_t)r0*N + cb + 1]   = c[mf][nf][1] + bias[cb+1];
            C[(size_t)(r0+8)*N + cb]   = c[mf][nf][2] + bias[cb];
            C[(size_t)(r0+8)*N + cb+1] = c[mf][nf][3] + bias[cb+1];
        }
    }
}

// ---------------- k_hw: h_w GEMM with FUSED LSTM epilogue in A-loader + hmem scatter ----
// WM=2,WN=2,MF=1,NF=4 -> BM=32, BN=64, 128 threads, grid (1, 64). 3-pass split.
#define HW_SMEM 30720
__global__ __launch_bounds__(128) void k_hw(
    const float* __restrict__ x, const float* __restrict__ cin,
    const float* __restrict__ bfc1, const int* __restrict__ memcnt,
    float* __restrict__ d_out, float* __restrict__ out_hmem) {
    constexpr int BK = 32, LDA = 40;
    constexpr int BM = 32, BN = 64, NT = 128;
    constexpr int ASZ = BM*LDA, BSZE = BN*LDA;
    constexpr int STAGE = (ASZ + BSZE) * 2;
    constexpr int MF = 1, NF = 4;
    extern __shared__ __align__(16) bf16 sm[];
    int tid = threadIdx.x;
    int w = tid >> 5, lane = tid & 31, g = lane >> 2, tg = lane & 3;
    int wm = w >> 1, wn = w & 1;
    int m0 = blockIdx.y*BM;
    const int KT = 768 / BK;   // 24
    float c[MF][NF][4] = {};

    uint32_t a_off = (uint32_t)(((((lane>>3)&1)*8 + (lane&7))*LDA + (lane>>4)*8) * 2);
    uint32_t b_off = (uint32_t)((((lane&7) + ((lane>>4)&1)*8)*LDA + ((lane>>3)&1)*8) * 2);

    float4 av[2];
    auto ldA = [&](int kt) {
        #pragma unroll
        for (int l = 0; l < 2; l++) {
            int i = tid + l*NT;
            int row = i >> 3, q = i & 7;
            int gr = m0 + row, kk = kt*BK + q*4;
            float4 v;
            if (kk < 256) {
                v = *(const float4*)&x[(size_t)gr*256 + kk];
            } else {
                int j = kk - 256;
                float4 gi = *(const float4*)&g_G[(size_t)gr*GN + j];
                float4 gf = *(const float4*)&g_G[(size_t)gr*GN + 512 + j];
                float4 go = *(const float4*)&g_G[(size_t)gr*GN + 1024 + j];
                float4 pp = *(const float4*)&g_P[(size_t)gr*HS + j];
                float4 cc = *(const float4*)&cin[(size_t)gr*HS + j];
                float4 nh;
                nh.x = tanhf(cc.x*sigm(gf.x+1.f) + sigm(gi.x)*tanhf(pp.x)) * sigm(go.x);
                nh.y = tanhf(cc.y*sigm(gf.y+1.f) + sigm(gi.y)*tanhf(pp.y)) * sigm(go.y);
                nh.z = tanhf(cc.z*sigm(gf.z+1.f) + sigm(gi.z)*tanhf(pp.z)) * sigm(go.z);
                nh.w = tanhf(cc.w*sigm(gf.w+1.f) + sigm(gi.w)*tanhf(pp.w)) * sigm(go.w);
                *(float4*)&d_out[(size_t)gr*OC + j] = nh;
                v = nh;
            }
            av[l] = v;
        }
    };
    auto stA = [&](int s) {
        bf16* Ah = sm + s*STAGE;
        bf16* Al = Ah + ASZ;
        #pragma unroll
        for (int l = 0; l < 2; l++) {
            int i = tid + l*NT;
            int row = i >> 3, q = i & 7;
            float4 v = av[l];
            uint32_t h0, l0, h1, l1;
            split2(v.x, v.y, h0, l0);
            split2(v.z, v.w, h1, l1);
            uint2 hh; hh.x = h0; hh.y = h1;
            uint2 ll; ll.x = l0; ll.y = l1;
            *(uint2*)&Ah[row*LDA + q*4] = hh;
            *(uint2*)&Al[row*LDA + q*4] = ll;
        }
    };
    auto ldB = [&](int s, int kt) {
        bf16* Bh = sm + s*STAGE + ASZ*2;
        bf16* Bl = Bh + BSZE;
        #pragma unroll
        for (int l = 0; l < 2; l++) {
            int i = tid + l*NT;
            int r = i >> 2, q = i & 3;
            CP_ASYNC16(sptr(&Bh[r*LDA + q*8]), &g_Ww_hi[(size_t)r*768 + kt*BK + q*8]);
            CP_ASYNC16(sptr(&Bl[r*LDA + q*8]), &g_Ww_lo[(size_t)r*768 + kt*BK + q*8]);
        }
    };

    ldA(0); ldB(0, 0); CP_COMMIT(); stA(0);
    CP_WAIT0(); __syncthreads();

    for (int kt = 0; kt < KT; kt++) {
        int s = kt & 1;
        bool nxt = (kt + 1 < KT);
        if (nxt) { ldB(s^1, kt+1); CP_COMMIT(); ldA(kt+1); }

        uint32_t ahb = sptr(sm + s*STAGE) + (uint32_t)(wm*16*LDA*2) + a_off;
        uint32_t alb = ahb + (uint32_t)(ASZ*2);
        uint32_t bhb = sptr(sm + s*STAGE + ASZ*2) + (uint32_t)(wn*NF*8*LDA*2) + b_off;
        uint32_t blb = bhb + (uint32_t)(BSZE*2);
        #pragma unroll
        for (int k0 = 0; k0 < BK; k0 += 16) {
            uint32_t ah[4], al[4];
            LDSM_X4(ah, ahb + (uint32_t)(k0*2));
            LDSM_X4(al, alb + (uint32_t)(k0*2));
            #pragma unroll
            for (int np = 0; np < NF/2; np++) {
                uint32_t bh[4], bl[4];
                LDSM_X4(bh, bhb + (uint32_t)((np*16*LDA + k0)*2));
                LDSM_X4(bl, blb + (uint32_t)((np*16*LDA + k0)*2));
                mma_bf16(c[0][2*np],   ah, bh[0], bh[1]);
                mma_bf16(c[0][2*np+1], ah, bh[2], bh[3]);
                mma_bf16(c[0][2*np],   al, bh[0], bh[1]);
                mma_bf16(c[0][2*np+1], al, bh[2], bh[3]);
                mma_bf16(c[0][2*np],   ah, bl[0], bl[1]);
                mma_bf16(c[0][2*np+1], ah, bl[2], bl[3]);
            }
        }
        if (nxt) stA(s^1);
        CP_WAIT0(); __syncthreads();
    }

    int mc = memcnt[0];
    int r0 = m0 + wm*16 + g;
    int row0 = (mc < MS) ? mc : g_idx[r0];
    int row1 = (mc < MS) ? mc : g_idx[r0+8];
    float* d0 = &out_hmem[((size_t)r0*MS + row0)*RS];
    float* d1 = &out_hmem[((size_t)(r0+8)*MS + row1)*RS];
    #pragma unroll
    for (int nf = 0; nf < NF; nf++) {
        int cb = wn*NF*8 + nf*8 + 2*tg;
        d0[cb]   = c[0][nf][0] + bfc1[cb];
        d0[cb+1] = c[0][nf][1] + bfc1[cb+1];
        d1[cb]   = c[0][nf][2] + bfc1[cb];
        d1[cb+1] = c[0][nf][3] + bfc1[cb+1];
    }
}

// ---------------- k_hid_mma: MMA + head + argmax + r + ab (shfl tail) ----------------
__global__ __launch_bounds__(256) void k_hid_mma(
    const float* __restrict__ hmem,
    const float* __restrict__ prev, const float* __restrict__ nsm,
    const float* __restrict__ x, const float* __restrict__ h,
    const float* __restrict__ W1, const float* __restrict__ b1,
    const float* __restrict__ nsig, float* __restrict__ d_out) {
    constexpr int LDA = 72;
    __shared__ __align__(16) bf16 As_hi[128*LDA];
    __shared__ __align__(16) bf16 Bs_hi[128*LDA];
    __shared__ float s_base[128], s_veca[128], s_head[128];
    __shared__ float redp[8], redq[8];
    __shared__ float svp[4];
    __shared__ int   sip[6];
    __shared__ float sh_r[64];
    int tid = threadIdx.x;
    int w = tid >> 5, lane = tid & 31, g = lane >> 2, tg = lane & 3;
    int wm = w >> 2, wn = w & 3;
    int b = blockIdx.x;

    const float4* src = (const float4*)(hmem + (size_t)b*8192);
    for (int i = tid; i < 2048; i += 256) {
        float4 v = src[i];
        int row = i >> 4, c4 = (i & 15) * 4;
        uint2 hh; hh.x = pack_hi2(v.x, v.y); hh.y = pack_hi2(v.z, v.w);
        *(uint2*)&As_hi[row*LDA + c4] = hh;
    }
    for (int i = tid; i < 1024; i += 256) {
        int r = i >> 3, q = i & 7;
        *(uint4*)&Bs_hi[r*LDA + q*8] = *(const uint4*)&g_Wm_hi[r*64 + q*8];
    }
    if (tid < 128) {
        s_base[tid] = g_base[(size_t)b*128 + tid];
        s_veca[tid] = g_veca[tid];
        s_head[tid] = 0.f;
    }
    __syncthreads();

    uint32_t a_lane_off = (uint32_t)(((((lane>>3)&1)*8 + (lane&7))*LDA + (lane>>4)*8) * 2);
    uint32_t as_base = sptr(As_hi) + (uint32_t)(wm*64*LDA*2) + a_lane_off;

    float c[4][4][4] = {};
    #pragma unroll
    for (int k0 = 0; k0 < 64; k0 += 16) {
        uint32_t ah[4][4];
        #pragma unroll
        for (int mf = 0; mf < 4; mf++)
            LDSM_X4(ah[mf], as_base + (uint32_t)((mf*16*LDA + k0)*2));
        #pragma unroll
        for (int nf = 0; nf < 4; nf++) {
            int nb = wn*32 + nf*8 + g;
            uint32_t bh0 = *(uint32_t*)&Bs_hi[nb*LDA + k0 + 2*tg];
            uint32_t bh1 = *(uint32_t*)&Bs_hi[nb*LDA + k0 + 8 + 2*tg];
            #pragma unroll
            for (int mf = 0; mf < 4; mf++) mma_bf16(c[mf][nf], ah[mf], bh0, bh1);
        }
    }

    #pragma unroll
    for (int mf = 0; mf < 4; mf++) {
        int r0 = wm*64 + mf*16 + g, r1 = r0 + 8;
        float hs0 = 0.f, hs1 = 0.f;
        #pragma unroll
        for (int nf = 0; nf < 4; nf++) {
            int cb = wn*32 + nf*8 + 2*tg;
            float v;
            v = c[mf][nf][0] + s_base[cb]   + g_keyW[r0*128 + cb];   hs0 += tanh_fast(v)*s_veca[cb];
            v = c[mf][nf][1] + s_base[cb+1] + g_keyW[r0*128 + cb+1]; hs0 += tanh_fast(v)*s_veca[cb+1];
            v = c[mf][nf][2] + s_base[cb]   + g_keyW[r1*128 + cb];   hs1 += tanh_fast(v)*s_veca[cb];
            v = c[mf][nf][3] + s_base[cb+1] + g_keyW[r1*128 + cb+1]; hs1 += tanh_fast(v)*s_veca[cb+1];
        }
        atomicAdd(&s_head[r0], hs0);
        atomicAdd(&s_head[r1], hs1);
    }
    __syncthreads();

    // --- warp-shuffle tail ---
    int t = tid;
    float val = 0.f, ss = 0.f;
    if (t < 128) {
        val = s_head[t] - 100.f * prev[b*128 + t];
        ss = val * val;
    }
    #pragma unroll
    for (int o = 16; o > 0; o >>= 1) ss += __shfl_xor_sync(0xffffffffu, ss, o);
    if (t < 128 && lane == 0) redp[w] = ss;
    __syncthreads();
    if (t < 128) {
        float norm = fmaxf(sqrtf(redp[0]+redp[1]+redp[2]+redp[3]), 1e-12f);
        float z = val / norm + gumbel(nsm[b*128 + t]);
        float bz = z; int bi = t;
        #pragma unroll
        for (int o = 16; o > 0; o >>= 1) {
            float oz = __shfl_xor_sync(0xffffffffu, bz, o);
            int   oi = __shfl_xor_sync(0xffffffffu, bi, o);
            if (oz > bz) { bz = oz; bi = oi; }
        }
        if (lane == 0) { svp[w] = bz; sip[w] = bi; }
    }
    __syncthreads();
    if (t == 0) {
        float bz = svp[0]; int bi = sip[0];
        #pragma unroll
        for (int j = 1; j < 4; j++) if (svp[j] > bz) { bz = svp[j]; bi = sip[j]; }
        sip[4] = bi;
        g_idx[b] = bi;
    }
    __syncthreads();
    int best = sip[4];
    if (t < 64) {
        float rv = hmem[((size_t)b*128 + best)*64 + t];
        g_r[b*64 + t] = rv;
        sh_r[t] = rv;
        d_out[(size_t)b*OC + 512 + t] = rv;
    }
    __syncthreads();
    float s0 = 0.f, s1 = 0.f;
    for (int k = t; k < CAT0; k += 256) {
        float a = (k < 256) ? x[b*256+k] : (k < 768) ? h[b*512 + (k-256)] : sh_r[k-768];
        s0 += a * W1[k*2];
        s1 += a * W1[k*2 + 1];
    }
    #pragma unroll
    for (int o = 16; o > 0; o >>= 1) {
        s0 += __shfl_xor_sync(0xffffffffu, s0, o);
        s1 += __shfl_xor_sync(0xffffffffu, s1, o);
    }
    if (lane == 0) { redp[w] = s0; redq[w] = s1; }
    __syncthreads();
    if (t == 0) {
        float a0 = 0.f, a1 = 0.f;
        #pragma unroll
        for (int j = 0; j < 8; j++) { a0 += redp[j]; a1 += redq[j]; }
        const float ST = (float)(10.0/3.0);
        g_ab[b*2]     = sigm((a0 + b1[0] + gumbel(nsig[b*2]))   * ST);
        g_ab[b*2 + 1] = sigm((a1 + b1[1] + gumbel(nsig[b*2+1])) * ST);
    }
}

// ---------------- launch ----------------
extern "C" void kernel_launch(void* const* d_in, const int* in_sizes, int n_in,
                              void* d_out, int out_size) {
    const float* x        = (const float*)d_in[0];
    const float* h        = (const float*)d_in[1];
    const float* c        = (const float*)d_in[2];
    const float* hmem     = (const float*)d_in[3];
    const float* u_t      = (const float*)d_in[4];
    const float* prev     = (const float*)d_in[5];
    const float* W_full   = (const float*)d_in[6];
    const float* bias     = (const float*)d_in[7];
    const float* W_full1  = (const float*)d_in[8];
    const float* bias1    = (const float*)d_in[9];
    const float* W_full2  = (const float*)d_in[10];
    const float* bias2    = (const float*)d_in[11];
    const float* keys     = (const float*)d_in[12];
    const float* vec_a    = (const float*)d_in[13];
    const float* W_fc     = (const float*)d_in[14];
    const float* b_fc     = (const float*)d_in[15];
    const float* W_fc1    = (const float*)d_in[16];
    const float* b_fc1    = (const float*)d_in[17];
    const float* noise_sm = (const float*)d_in[18];
    const float* noise_sig= (const float*)d_in[19];
    const int*   memcnt   = (const int*)d_in[20];

    float* out      = (float*)d_out;
    float* out_hmem = out + (size_t)BSZ * OC;

    float *pbase, *puinv;
    bf16 *pWbh;
    cudaGetSymbolAddress((void**)&pbase, g_base);
    cudaGetSymbolAddress((void**)&puinv, g_uinv);
    cudaGetSymbolAddress((void**)&pWbh,  g_Wb_hi);

    auto kBase = mgemm_base<2,4,1,2>;  // 32x64 tile, 1-pass
    cudaFuncSetAttribute((const void*)k_gp,  cudaFuncAttributeMaxDynamicSharedMemorySize, GP_SMEM);
    cudaFuncSetAttribute((const void*)kBase, cudaFuncAttributeMaxDynamicSharedMemorySize, 15360);
    cudaFuncSetAttribute((const void*)k_hw,  cudaFuncAttributeMaxDynamicSharedMemorySize, HW_SMEM);

    // 1. all prep
    k_prep<<<T_ALL, 256>>>(W_full, W_full2, W_fc, W_fc1, keys, vec_a, u_t);
    // 2. base = [x,c,u^]@Wb + b_fc
    kBase<<<dim3(2, BSZ/32), 256, 15360>>>(
        x, c, u_t, puinv, pWbh, pbase, b_fc, 128, XCU);
    // 3. hid + head + argmax + r + ab
    k_hid_mma<<<BSZ, 256>>>(hmem, prev, noise_sm, x, h, W_full1, bias1, noise_sig, out);
    // 4. merged G + P GEMM + interleaved hmem copy
    k_gp<<<dim3(GP_NGX + HS/64, BSZ/128), 256, GP_SMEM>>>(x, h, bias, bias2, hmem, out_hmem);
    // 5. h_w GEMM with fused LSTM epilogue (writes new_h to d_out) + hmem row scatter
    k_hw<<<dim3(1, BSZ/32), 128, HW_SMEM>>>(x, c, b_fc1, memcnt, out, out_hmem);
    (void)in_sizes; (void)n_in; (void)out_size;
}

// round 9
// speedup vs baseline: 1.0001x; 1.0001x over previous
#include <cuda_runtime.h>
#include <cuda_bf16.h>
#include <math.h>
#include <stdint.h>

#define BSZ 2048
#define HS  512
#define RS  64
#define MS  128
#define CAT0 832
#define XCU 896
#define GN  1536
#define OC  576

typedef __nv_bfloat16 bf16;

// ---------------- scratch (device globals; no allocations) ----------------
__device__ __align__(16) float g_base [BSZ*128];
__device__ __align__(16) float g_keyW [128*128];
__device__ __align__(16) float g_ab   [BSZ*2];
__device__             int   g_idx  [BSZ];
__device__ __align__(16) float g_r    [BSZ*RS];
__device__ __align__(16) float g_G    [BSZ*GN];
__device__ __align__(16) float g_P    [BSZ*HS];
__device__ __align__(16) float g_veca [128];
__device__ __align__(16) float g_uinv [BSZ];
__device__ __align__(16) bf16 g_WG_hi[GN*CAT0],  g_WG_lo[GN*CAT0];
__device__ __align__(16) bf16 g_WP_hi[HS*CAT0],  g_WP_lo[HS*CAT0];
__device__ __align__(16) bf16 g_Wb_hi[128*XCU];
__device__ __align__(16) bf16 g_Ww_hi[64*768],   g_Ww_lo[64*768];
__device__ __align__(16) bf16 g_Wm_hi[128*64];

__device__ __forceinline__ float tanh_fast(float x) {
    float y; asm("tanh.approx.f32 %0, %1;" : "=f"(y) : "f"(x)); return y;
}
__device__ __forceinline__ float sigm(float x) { return 1.f/(1.f+expf(-x)); }
__device__ __forceinline__ float gumbel(float u) {
    return -logf(1e-20f - logf(1e-20f + u));
}
__device__ __forceinline__ void split2(float a, float b, uint32_t& hi, uint32_t& lo) {
    __nv_bfloat162 h, l;
    h.x = __float2bfloat16(a); h.y = __float2bfloat16(b);
    l.x = __float2bfloat16(a - __bfloat162float(h.x));
    l.y = __float2bfloat16(b - __bfloat162float(h.y));
    hi = *(uint32_t*)&h; lo = *(uint32_t*)&l;
}
__device__ __forceinline__ uint32_t pack_hi2(float a, float b) {
    __nv_bfloat162 h; h.x = __float2bfloat16(a); h.y = __float2bfloat16(b);
    return *(uint32_t*)&h;
}
__device__ __forceinline__ void mma_bf16(float* c, const uint32_t* a, uint32_t b0, uint32_t b1) {
    asm volatile("mma.sync.aligned.m16n8k16.row.col.f32.bf16.bf16.f32 "
        "{%0,%1,%2,%3},{%4,%5,%6,%7},{%8,%9},{%0,%1,%2,%3};"
        : "+f"(c[0]), "+f"(c[1]), "+f"(c[2]), "+f"(c[3])
        : "r"(a[0]), "r"(a[1]), "r"(a[2]), "r"(a[3]), "r"(b0), "r"(b1));
}
#define LDSM_X4(r, addr) \
    asm volatile("ldmatrix.sync.aligned.m8n8.x4.shared.b16 {%0,%1,%2,%3}, [%4];" \
        : "=r"((r)[0]), "=r"((r)[1]), "=r"((r)[2]), "=r"((r)[3]) : "r"(addr))
#define CP_ASYNC16(saddr, gptr) \
    asm volatile("cp.async.cg.shared.global [%0], [%1], 16;" :: "r"(saddr), "l"(gptr))
#define CP_COMMIT() asm volatile("cp.async.commit_group;" ::: "memory")
#define CP_WAIT0()  asm volatile("cp.async.wait_group 0;" ::: "memory")
__device__ __forceinline__ uint32_t sptr(const void* p) {
    return (uint32_t)__cvta_generic_to_shared(p);
}

// ---------------- k_prep ----------------
__device__ void tsplit_tile(const float* __restrict__ src, bf16* __restrict__ dhi,
                            bf16* __restrict__ dlo, int K, int N, int split, int extra,
                            int tile, int tid) {
    __shared__ float t[32][33];
    int nt = N/32;
    int n0 = (tile % nt)*32, k0 = (tile / nt)*32;
    int tx = tid & 31, ty = tid >> 5;
    for (int r = ty; r < 32; r += 8) {
        int k = k0 + r; int sr = (k < split) ? k : k + extra;
        t[r][tx] = src[(size_t)sr*N + n0 + tx];
    }
    __syncthreads();
    for (int r = ty; r < 32; r += 8) {
        float v = t[tx][r];
        bf16 hi = __float2bfloat16(v);
        size_t o = (size_t)(n0 + r)*K + k0 + tx;
        dhi[o] = hi;
        if (dlo) dlo[o] = __float2bfloat16(v - __bfloat162float(hi));
    }
}

#define T_WG 1248
#define T_WP (T_WG + 416)
#define T_WB (T_WP + 112)
#define T_WW (T_WB + 48)
#define T_WM (T_WW + 8)
#define T_KW (T_WM + 64)
#define T_UN (T_KW + 256)
#define T_ALL (T_UN + 1)

__global__ __launch_bounds__(256) void k_prep(
    const float* __restrict__ W_full, const float* __restrict__ W_full2,
    const float* __restrict__ W_fc,   const float* __restrict__ W_fc1,
    const float* __restrict__ keys,   const float* __restrict__ vec_a,
    const float* __restrict__ u) {
    int blk = blockIdx.x, tid = threadIdx.x;
    if (blk < T_WG) {
        tsplit_tile(W_full, g_WG_hi, g_WG_lo, CAT0, GN, CAT0, 0, blk, tid);
    } else if (blk < T_WP) {
        tsplit_tile(W_full2, g_WP_hi, g_WP_lo, CAT0, HS, CAT0, 0, blk - T_WG, tid);
    } else if (blk < T_WB) {
        tsplit_tile(W_fc, g_Wb_hi, nullptr, XCU, 128, 768, 128, blk - T_WP, tid);
    } else if (blk < T_WW) {
        tsplit_tile(W_fc1, g_Ww_hi, g_Ww_lo, 768, 64, 768, 0, blk - T_WB, tid);
    } else if (blk < T_WM) {
        tsplit_tile(W_fc + 832*128, g_Wm_hi, nullptr, 64, 128, 64, 0, blk - T_WW, tid);
    } else if (blk < T_KW) {
        __shared__ float krow[2][64];
        int sub = tid >> 7, t = tid & 127;
        int m = (blk - T_WM)*2 + sub;
        if (t < 64) krow[sub][t] = keys[m*64 + t];
        __syncthreads();
        float acc = 0.f;
        #pragma unroll 8
        for (int r = 0; r < 64; r++) acc += krow[sub][r] * W_fc[(768+r)*128 + t];
        g_keyW[m*128 + t] = acc;
    } else if (blk < T_UN) {
        int w = tid >> 5, lane = tid & 31;
        int b = (blk - T_KW)*8 + w;
        float s = 0.f;
        #pragma unroll
        for (int j = lane; j < 128; j += 32) { float v = u[b*128+j]; s += v*v; }
        #pragma unroll
        for (int o = 16; o > 0; o >>= 1) s += __shfl_down_sync(0xffffffffu, s, o);
        if (lane == 0) g_uinv[b] = 1.f / fmaxf(sqrtf(s), 1e-12f);
    } else {
        if (tid < 128) g_veca[tid] = vec_a[tid];
    }
}

// ---------------- k_gp: merged G+P GEMM + interleaved hmem copy ----------------
#define GP_NGX 24
#define GP_SMEM 61440
__global__ __launch_bounds__(256, 2) void k_gp(
    const float* __restrict__ x, const float* __restrict__ h,
    const float* __restrict__ biasG, const float* __restrict__ bias2,
    const float* __restrict__ hmem, float* __restrict__ out_hmem) {
    constexpr int BK = 32, LDA = 40;
    constexpr int BM = 128, BN = 64;
    constexpr int ASZ = BM*LDA, BSZE = BN*LDA;
    constexpr int STAGE = (ASZ + BSZE) * 2;
    constexpr int MF = 2, NF = 4;
    extern __shared__ __align__(16) bf16 sm[];
    int tid = threadIdx.x;
    int w = tid >> 5, lane = tid & 31, g = lane >> 2, tg = lane & 3;
    int wm = w >> 1, wn = w & 1;
    bool isP = blockIdx.x >= GP_NGX;
    int n0 = (isP ? (int)blockIdx.x - GP_NGX : (int)blockIdx.x) * BN;
    int m0 = blockIdx.y * BM;
    const bf16* BT_hi = isP ? g_WP_hi : g_WG_hi;
    const bf16* BT_lo = isP ? g_WP_lo : g_WG_lo;
    const int KT = CAT0 / BK;   // 26
    float c[MF][NF][4] = {};

    // distributed hmem copy: 8192 float4 per block, 512 per k-iteration (16 iters)
    size_t cbase = ((size_t)(blockIdx.y * gridDim.x + blockIdx.x)) * 8192;
    const float4* csrc = (const float4*)hmem;
    float4* cdst = (float4*)out_hmem;
    float4 cb0, cb1;

    uint32_t a_off = (uint32_t)(((((lane>>3)&1)*8 + (lane&7))*LDA + (lane>>4)*8) * 2);
    uint32_t b_off = (uint32_t)((((lane&7) + ((lane>>4)&1)*8)*LDA + ((lane>>3)&1)*8) * 2);

    // A tile: 128 rows x 32 cols. Each thread: 2 pair-loads of 8 floats from one row.
    float4 av0[2], av1[2];
    auto ldA = [&](int kt) {
        #pragma unroll
        for (int l = 0; l < 2; l++) {
            int i = tid + l*256;
            int row = i >> 2, p = i & 3;
            int gr = m0 + row, kk = kt*BK + p*8;
            float4 v0, v1;
            if (kk < 256) {
                v0 = *(const float4*)&x[(size_t)gr*256 + kk];
                v1 = *(const float4*)&x[(size_t)gr*256 + kk + 4];
            } else if (kk < 768) {
                v0 = *(const float4*)&h[(size_t)gr*512 + kk-256];
                v1 = *(const float4*)&h[(size_t)gr*512 + kk-252];
            } else {
                v0 = *(const float4*)&g_r[(size_t)gr*64 + kk-768];
                v1 = *(const float4*)&g_r[(size_t)gr*64 + kk-764];
            }
            if (isP) {
                float s = (kk >= 768) ? g_ab[gr*2+1] : (kk >= 256) ? g_ab[gr*2] : 1.f;
                v0.x *= s; v0.y *= s; v0.z *= s; v0.w *= s;
                v1.x *= s; v1.y *= s; v1.z *= s; v1.w *= s;
            }
            av0[l] = v0; av1[l] = v1;
        }
    };
    auto stA = [&](int s) {
        bf16* Ah = sm + s*STAGE;
        bf16* Al = Ah + ASZ;
        #pragma unroll
        for (int l = 0; l < 2; l++) {
            int i = tid + l*256;
            int row = i >> 2, p = i & 3;
            float4 v0 = av0[l], v1 = av1[l];
            uint4 hi, lo;
            split2(v0.x, v0.y, hi.x, lo.x);
            split2(v0.z, v0.w, hi.y, lo.y);
            split2(v1.x, v1.y, hi.z, lo.z);
            split2(v1.z, v1.w, hi.w, lo.w);
            *(uint4*)&Ah[row*LDA + p*8] = hi;
            *(uint4*)&Al[row*LDA + p*8] = lo;
        }
    };
    auto ldB = [&](int s, int kt) {
        bf16* Bh = sm + s*STAGE + ASZ*2;
        bf16* Bl = Bh + BSZE;
        int r = tid >> 2, q = tid & 3;
        CP_ASYNC16(sptr(&Bh[r*LDA + q*8]), &BT_hi[(size_t)(n0+r)*CAT0 + kt*BK + q*8]);
        CP_ASYNC16(sptr(&Bl[r*LDA + q*8]), &BT_lo[(size_t)(n0+r)*CAT0 + kt*BK + q*8]);
    };

    ldA(0); ldB(0, 0); CP_COMMIT(); stA(0);
    cb0 = csrc[cbase + tid];
    cb1 = csrc[cbase + 256 + tid];
    CP_WAIT0(); __syncthreads();

    for (int kt = 0; kt < KT; kt++) {
        int s = kt & 1;
        bool nxt = (kt + 1 < KT);
        if (nxt) { ldB(s^1, kt+1); CP_COMMIT(); ldA(kt+1); }
        if (kt < 16) {
            size_t o = cbase + (size_t)kt*512 + tid;
            cdst[o] = cb0;
            cdst[o + 256] = cb1;
            if (kt + 1 < 16) {
                size_t o2 = o + 512;
                cb0 = csrc[o2];
                cb1 = csrc[o2 + 256];
            }
        }

        uint32_t ahb = sptr(sm + s*STAGE) + (uint32_t)(wm*MF*16*LDA*2) + a_off;
        uint32_t alb = ahb + (uint32_t)(ASZ*2);
        uint32_t bhb = sptr(sm + s*STAGE + ASZ*2) + (uint32_t)(wn*NF*8*LDA*2) + b_off;
        uint32_t blb = bhb + (uint32_t)(BSZE*2);
        #pragma unroll
        for (int k0 = 0; k0 < BK; k0 += 16) {
            uint32_t ah[MF][4], al[MF][4];
            #pragma unroll
            for (int mf = 0; mf < MF; mf++) {
                LDSM_X4(ah[mf], ahb + (uint32_t)((mf*16*LDA + k0)*2));
                LDSM_X4(al[mf], alb + (uint32_t)((mf*16*LDA + k0)*2));
            }
            #pragma unroll
            for (int np = 0; np < NF/2; np++) {
                uint32_t bh[4], bl[4];
                LDSM_X4(bh, bhb + (uint32_t)((np*16*LDA + k0)*2));
                LDSM_X4(bl, blb + (uint32_t)((np*16*LDA + k0)*2));
                #pragma unroll
                for (int mf = 0; mf < MF; mf++) {
                    mma_bf16(c[mf][2*np],   ah[mf], bh[0], bh[1]);
                    mma_bf16(c[mf][2*np+1], ah[mf], bh[2], bh[3]);
                    mma_bf16(c[mf][2*np],   al[mf], bh[0], bh[1]);
                    mma_bf16(c[mf][2*np+1], al[mf], bh[2], bh[3]);
                    mma_bf16(c[mf][2*np],   ah[mf], bl[0], bl[1]);
                    mma_bf16(c[mf][2*np+1], ah[mf], bl[2], bl[3]);
                }
            }
        }
        if (nxt) stA(s^1);
        CP_WAIT0(); __syncthreads();
    }

    float* C = isP ? g_P : g_G;
    const float* bias = isP ? bias2 : biasG;
    int N = isP ? HS : GN;
    #pragma unroll
    for (int mf = 0; mf < MF; mf++) {
        int r0 = m0 + wm*MF*16 + mf*16 + g;
        #pragma unroll
        for (int nf = 0; nf < NF; nf++) {
            int cb = n0 + wn*NF*8 + nf*8 + 2*tg;
            C[(size_t)r0*N + cb]       = c[mf][nf][0] + bias[cb];
            C[(size_t)r0*N + cb + 1]   = c[mf][nf][1] + bias[cb+1];
            C[(size_t)(r0+8)*N + cb]   = c[mf][nf][2] + bias[cb];
            C[(size_t)(r0+8)*N + cb+1] = c[mf][nf][3] + bias[cb+1];
        }
    }
}

// ---------------- generic pipelined GEMM (base) ----------------
template<int WM, int WN, int MF, int NF>
__global__ __launch_bounds__(WM*WN*32) void mgemm_base(
    const float* __restrict__ p0, const float* __restrict__ p1,
    const float* __restrict__ p2, const float* __restrict__ aux,
    const bf16* __restrict__ BT_hi,
    float* __restrict__ C, const float* __restrict__ bias, int N, int K) {
    constexpr int BK = 32, LDA = 40;
    constexpr int BM = WM*MF*16, BN = WN*NF*8, NT = WM*WN*32;
    constexpr int ASZ = BM*LDA, BSZE = BN*LDA;
    constexpr int STAGE = ASZ + BSZE;
    constexpr int ALOADS = BM*BK/4/NT;
    constexpr int BCHUNK = BN*BK/8/NT;
    extern __shared__ __align__(16) bf16 sm[];
    int tid = threadIdx.x;
    int w = tid >> 5, lane = tid & 31, g = lane >> 2, tg = lane & 3;
    int wm = w / WN, wn = w % WN;
    int m0 = blockIdx.y*BM, n0 = blockIdx.x*BN;
    const int KT = K / BK;
    float c[MF][NF][4] = {};

    uint32_t a_off = (uint32_t)(((((lane>>3)&1)*8 + (lane&7))*LDA + (lane>>4)*8) * 2);
    uint32_t b_off = (uint32_t)((((lane&7) + ((lane>>4)&1)*8)*LDA + ((lane>>3)&1)*8) * 2);

    float4 av[ALOADS];
    auto ldA = [&](int kt) {
        #pragma unroll
        for (int l = 0; l < ALOADS; l++) {
            int i = tid + l*NT;
            int row = i/(BK/4), q = i%(BK/4);
            int gr = m0 + row, kk = kt*BK + q*4;
            float4 v;
            if (kk < 256)      v = *(const float4*)&p0[(size_t)gr*256 + kk];
            else if (kk < 768) v = *(const float4*)&p1[(size_t)gr*512 + kk-256];
            else {
                v = *(const float4*)&p2[(size_t)gr*128 + kk-768];
                float s = aux[gr];
                v.x *= s; v.y *= s; v.z *= s; v.w *= s;
            }
            av[l] = v;
        }
    };
    auto stA = [&](int s) {
        bf16* Ah = sm + s*STAGE;
        #pragma unroll
        for (int l = 0; l < ALOADS; l++) {
            int i = tid + l*NT;
            int row = i/(BK/4), q = i%(BK/4);
            float4 v = av[l];
            uint2 hh; hh.x = pack_hi2(v.x, v.y); hh.y = pack_hi2(v.z, v.w);
            *(uint2*)&Ah[row*LDA + q*4] = hh;
        }
    };
    auto ldB = [&](int s, int kt) {
        bf16* Bh = sm + s*STAGE + ASZ;
        #pragma unroll
        for (int l = 0; l < BCHUNK; l++) {
            int i = tid + l*NT;
            int r = i/(BK/8), q = i%(BK/8);
            CP_ASYNC16(sptr(&Bh[r*LDA + q*8]), &BT_hi[(size_t)(n0+r)*K + kt*BK + q*8]);
        }
    };

    ldA(0); ldB(0, 0); CP_COMMIT(); stA(0);
    CP_WAIT0(); __syncthreads();

    for (int kt = 0; kt < KT; kt++) {
        int s = kt & 1;
        bool nxt = (kt + 1 < KT);
        if (nxt) { ldB(s^1, kt+1); CP_COMMIT(); ldA(kt+1); }

        uint32_t ahb = sptr(sm + s*STAGE) + (uint32_t)(wm*MF*16*LDA*2) + a_off;
        uint32_t bhb = sptr(sm + s*STAGE + ASZ) + (uint32_t)(wn*NF*8*LDA*2) + b_off;
        #pragma unroll
        for (int k0 = 0; k0 < BK; k0 += 16) {
            uint32_t ah[MF][4];
            #pragma unroll
            for (int mf = 0; mf < MF; mf++)
                LDSM_X4(ah[mf], ahb + (uint32_t)((mf*16*LDA + k0)*2));
            #pragma unroll
            for (int np = 0; np < NF/2; np++) {
                uint32_t bh[4];
                LDSM_X4(bh, bhb + (uint32_t)((np*16*LDA + k0)*2));
                #pragma unroll
                for (int mf = 0; mf < MF; mf++) {
                    mma_bf16(c[mf][2*np],   ah[mf], bh[0], bh[1]);
                    mma_bf16(c[mf][2*np+1], ah[mf], bh[2], bh[3]);
                }
            }
        }
        if (nxt) stA(s^1);
        CP_WAIT0(); __syncthreads();
    }

    #pragma unroll
    for (int mf = 0; mf < MF; mf++) {
        int r0 = m0 + wm*MF*16 + mf*16 + g;
        #pragma unroll
        for (int nf = 0; nf < NF; nf++) {
            int cb = n0 + wn*NF*8 + nf*8 + 2*tg;
            C[(size_t)r0*N + cb]       = c[mf][nf][0] + bias[cb];
            C[(size_t)r0*N + cb + 1]   = c[mf][nf][1] + bias[cb+1];
            C[(size_t)(r0+8)*N + cb]   = c[mf][nf][2] + bias[cb];
            C[(size_t)(r0+8)*N + cb+1] = c[mf][nf][3] + bias[cb+1];
        }
    }
}

// ---------------- k_hw: h_w GEMM with FUSED LSTM epilogue in A-loader + hmem scatter ----
// WM=2,WN=2,MF=1,NF=4 -> BM=32, BN=64, 128 threads, grid (1, 64). 3-pass split.
#define HW_SMEM 30720
__global__ __launch_bounds__(128) void k_hw(
    const float* __restrict__ x, const float* __restrict__ cin,
    const float* __restrict__ bfc1, const int* __restrict__ memcnt,
    float* __restrict__ d_out, float* __restrict__ out_hmem) {
    constexpr int BK = 32, LDA = 40;
    constexpr int BM = 32, BN = 64, NT = 128;
    constexpr int ASZ = BM*LDA, BSZE = BN*LDA;
    constexpr int STAGE = (ASZ + BSZE) * 2;
    constexpr int MF = 1, NF = 4;
    extern __shared__ __align__(16) bf16 sm[];
    int tid = threadIdx.x;
    int w = tid >> 5, lane = tid & 31, g = lane >> 2, tg = lane & 3;
    int wm = w >> 1, wn = w & 1;
    int m0 = blockIdx.y*BM;
    const int KT = 768 / BK;   // 24
    float c[MF][NF][4] = {};

    uint32_t a_off = (uint32_t)(((((lane>>3)&1)*8 + (lane&7))*LDA + (lane>>4)*8) * 2);
    uint32_t b_off = (uint32_t)((((lane&7) + ((lane>>4)&1)*8)*LDA + ((lane>>3)&1)*8) * 2);

    float4 av[2];
    auto ldA = [&](int kt) {
        #pragma unroll
        for (int l = 0; l < 2; l++) {
            int i = tid + l*NT;
            int row = i >> 3, q = i & 7;
            int gr = m0 + row, kk = kt*BK + q*4;
            float4 v;
            if (kk < 256) {
                v = *(const float4*)&x[(size_t)gr*256 + kk];
            } else {
                int j = kk - 256;
                float4 gi = *(const float4*)&g_G[(size_t)gr*GN + j];
                float4 gf = *(const float4*)&g_G[(size_t)gr*GN + 512 + j];
                float4 go = *(const float4*)&g_G[(size_t)gr*GN + 1024 + j];
                float4 pp = *(const float4*)&g_P[(size_t)gr*HS + j];
                float4 cc = *(const float4*)&cin[(size_t)gr*HS + j];
                float4 nh;
                nh.x = tanhf(cc.x*sigm(gf.x+1.f) + sigm(gi.x)*tanhf(pp.x)) * sigm(go.x);
                nh.y = tanhf(cc.y*sigm(gf.y+1.f) + sigm(gi.y)*tanhf(pp.y)) * sigm(go.y);
                nh.z = tanhf(cc.z*sigm(gf.z+1.f) + sigm(gi.z)*tanhf(pp.z)) * sigm(go.z);
                nh.w = tanhf(cc.w*sigm(gf.w+1.f) + sigm(gi.w)*tanhf(pp.w)) * sigm(go.w);
                *(float4*)&d_out[(size_t)gr*OC + j] = nh;
                v = nh;
            }
            av[l] = v;
        }
    };
    auto stA = [&](int s) {
        bf16* Ah = sm + s*STAGE;
        bf16* Al = Ah + ASZ;
        #pragma unroll
        for (int l = 0; l < 2; l++) {
            int i = tid + l*NT;
            int row = i >> 3, q = i & 7;
            float4 v = av[l];
            uint32_t h0, l0, h1, l1;
            split2(v.x, v.y, h0, l0);
            split2(v.z, v.w, h1, l1);
            uint2 hh; hh.x = h0; hh.y = h1;
            uint2 ll; ll.x = l0; ll.y = l1;
            *(uint2*)&Ah[row*LDA + q*4] = hh;
            *(uint2*)&Al[row*LDA + q*4] = ll;
        }
    };
    auto ldB = [&](int s, int kt) {
        bf16* Bh = sm + s*STAGE + ASZ*2;
        bf16* Bl = Bh + BSZE;
        #pragma unroll
        for (int l = 0; l < 2; l++) {
            int i = tid + l*NT;
            int r = i >> 2, q = i & 3;
            CP_ASYNC16(sptr(&Bh[r*LDA + q*8]), &g_Ww_hi[(size_t)r*768 + kt*BK + q*8]);
            CP_ASYNC16(sptr(&Bl[r*LDA + q*8]), &g_Ww_lo[(size_t)r*768 + kt*BK + q*8]);
        }
    };

    ldA(0); ldB(0, 0); CP_COMMIT(); stA(0);
    CP_WAIT0(); __syncthreads();

    for (int kt = 0; kt < KT; kt++) {
        int s = kt & 1;
        bool nxt = (kt + 1 < KT);
        if (nxt) { ldB(s^1, kt+1); CP_COMMIT(); ldA(kt+1); }

        uint32_t ahb = sptr(sm + s*STAGE) + (uint32_t)(wm*16*LDA*2) + a_off;
        uint32_t alb = ahb + (uint32_t)(ASZ*2);
        uint32_t bhb = sptr(sm + s*STAGE + ASZ*2) + (uint32_t)(wn*NF*8*LDA*2) + b_off;
        uint32_t blb = bhb + (uint32_t)(BSZE*2);
        #pragma unroll
        for (int k0 = 0; k0 < BK; k0 += 16) {
            uint32_t ah[4], al[4];
            LDSM_X4(ah, ahb + (uint32_t)(k0*2));
            LDSM_X4(al, alb + (uint32_t)(k0*2));
            #pragma unroll
            for (int np = 0; np < NF/2; np++) {
                uint32_t bh[4], bl[4];
                LDSM_X4(bh, bhb + (uint32_t)((np*16*LDA + k0)*2));
                LDSM_X4(bl, blb + (uint32_t)((np*16*LDA + k0)*2));
                mma_bf16(c[0][2*np],   ah, bh[0], bh[1]);
                mma_bf16(c[0][2*np+1], ah, bh[2], bh[3]);
                mma_bf16(c[0][2*np],   al, bh[0], bh[1]);
                mma_bf16(c[0][2*np+1], al, bh[2], bh[3]);
                mma_bf16(c[0][2*np],   ah, bl[0], bl[1]);
                mma_bf16(c[0][2*np+1], ah, bl[2], bl[3]);
            }
        }
        if (nxt) stA(s^1);
        CP_WAIT0(); __syncthreads();
    }

    int mc = memcnt[0];
    int r0 = m0 + wm*16 + g;
    int row0 = (mc < MS) ? mc : g_idx[r0];
    int row1 = (mc < MS) ? mc : g_idx[r0+8];
    float* d0 = &out_hmem[((size_t)r0*MS + row0)*RS];
    float* d1 = &out_hmem[((size_t)(r0+8)*MS + row1)*RS];
    #pragma unroll
    for (int nf = 0; nf < NF; nf++) {
        int cb = wn*NF*8 + nf*8 + 2*tg;
        d0[cb]   = c[0][nf][0] + bfc1[cb];
        d0[cb+1] = c[0][nf][1] + bfc1[cb+1];
        d1[cb]   = c[0][nf][2] + bfc1[cb];
        d1[cb+1] = c[0][nf][3] + bfc1[cb+1];
    }
}

// ---------------- k_hid_mma: MMA + head + argmax + r + ab (shfl tail) ----------------
__global__ __launch_bounds__(256) void k_hid_mma(
    const float* __restrict__ hmem,
    const float* __restrict__ prev, const float* __restrict__ nsm,
    const float* __restrict__ x, const float* __restrict__ h,
    const float* __restrict__ W1, const float* __restrict__ b1,
    const float* __restrict__ nsig, float* __restrict__ d_out) {
    constexpr int LDA = 72;
    __shared__ __align__(16) bf16 As_hi[128*LDA];
    __shared__ __align__(16) bf16 Bs_hi[128*LDA];
    __shared__ float s_base[128], s_veca[128], s_head[128];
    __shared__ float redp[8], redq[8];
    __shared__ float svp[4];
    __shared__ int   sip[6];
    __shared__ float sh_r[64];
    int tid = threadIdx.x;
    int w = tid >> 5, lane = tid & 31, g = lane >> 2, tg = lane & 3;
    int wm = w >> 2, wn = w & 3;
    int b = blockIdx.x;

    const float4* src = (const float4*)(hmem + (size_t)b*8192);
    for (int i = tid; i < 2048; i += 256) {
        float4 v = src[i];
        int row = i >> 4, c4 = (i & 15) * 4;
        uint2 hh; hh.x = pack_hi2(v.x, v.y); hh.y = pack_hi2(v.z, v.w);
        *(uint2*)&As_hi[row*LDA + c4] = hh;
    }
    for (int i = tid; i < 1024; i += 256) {
        int r = i >> 3, q = i & 7;
        *(uint4*)&Bs_hi[r*LDA + q*8] = *(const uint4*)&g_Wm_hi[r*64 + q*8];
    }
    if (tid < 128) {
        s_base[tid] = g_base[(size_t)b*128 + tid];
        s_veca[tid] = g_veca[tid];
        s_head[tid] = 0.f;
    }
    __syncthreads();

    uint32_t a_lane_off = (uint32_t)(((((lane>>3)&1)*8 + (lane&7))*LDA + (lane>>4)*8) * 2);
    uint32_t as_base = sptr(As_hi) + (uint32_t)(wm*64*LDA*2) + a_lane_off;

    float c[4][4][4] = {};
    #pragma unroll
    for (int k0 = 0; k0 < 64; k0 += 16) {
        uint32_t ah[4][4];
        #pragma unroll
        for (int mf = 0; mf < 4; mf++)
            LDSM_X4(ah[mf], as_base + (uint32_t)((mf*16*LDA + k0)*2));
        #pragma unroll
        for (int nf = 0; nf < 4; nf++) {
            int nb = wn*32 + nf*8 + g;
            uint32_t bh0 = *(uint32_t*)&Bs_hi[nb*LDA + k0 + 2*tg];
            uint32_t bh1 = *(uint32_t*)&Bs_hi[nb*LDA + k0 + 8 + 2*tg];
            #pragma unroll
            for (int mf = 0; mf < 4; mf++) mma_bf16(c[mf][nf], ah[mf], bh0, bh1);
        }
    }

    #pragma unroll
    for (int mf = 0; mf < 4; mf++) {
        int r0 = wm*64 + mf*16 + g, r1 = r0 + 8;
        float hs0 = 0.f, hs1 = 0.f;
        #pragma unroll
        for (int nf = 0; nf < 4; nf++) {
            int cb = wn*32 + nf*8 + 2*tg;
            float v;
            v = c[mf][nf][0] + s_base[cb]   + g_keyW[r0*128 + cb];   hs0 += tanh_fast(v)*s_veca[cb];
            v = c[mf][nf][1] + s_base[cb+1] + g_keyW[r0*128 + cb+1]; hs0 += tanh_fast(v)*s_veca[cb+1];
            v = c[mf][nf][2] + s_base[cb]   + g_keyW[r1*128 + cb];   hs1 += tanh_fast(v)*s_veca[cb];
            v = c[mf][nf][3] + s_base[cb+1] + g_keyW[r1*128 + cb+1]; hs1 += tanh_fast(v)*s_veca[cb+1];
        }
        atomicAdd(&s_head[r0], hs0);
        atomicAdd(&s_head[r1], hs1);
    }
    __syncthreads();

    // --- warp-shuffle tail ---
    int t = tid;
    float val = 0.f, ss = 0.f;
    if (t < 128) {
        val = s_head[t] - 100.f * prev[b*128 + t];
        ss = val * val;
    }
    #pragma unroll
    for (int o = 16; o > 0; o >>= 1) ss += __shfl_xor_sync(0xffffffffu, ss, o);
    if (t < 128 && lane == 0) redp[w] = ss;
    __syncthreads();
    if (t < 128) {
        float norm = fmaxf(sqrtf(redp[0]+redp[1]+redp[2]+redp[3]), 1e-12f);
        float z = val / norm + gumbel(nsm[b*128 + t]);
        float bz = z; int bi = t;
        #pragma unroll
        for (int o = 16; o > 0; o >>= 1) {
            float oz = __shfl_xor_sync(0xffffffffu, bz, o);
            int   oi = __shfl_xor_sync(0xffffffffu, bi, o);
            if (oz > bz) { bz = oz; bi = oi; }
        }
        if (lane == 0) { svp[w] = bz; sip[w] = bi; }
    }
    __syncthreads();
    if (t == 0) {
        float bz = svp[0]; int bi = sip[0];
        #pragma unroll
        for (int j = 1; j < 4; j++) if (svp[j] > bz) { bz = svp[j]; bi = sip[j]; }
        sip[4] = bi;
        g_idx[b] = bi;
    }
    __syncthreads();
    int best = sip[4];
    if (t < 64) {
        float rv = hmem[((size_t)b*128 + best)*64 + t];
        g_r[b*64 + t] = rv;
        sh_r[t] = rv;
        d_out[(size_t)b*OC + 512 + t] = rv;
    }
    __syncthreads();
    float s0 = 0.f, s1 = 0.f;
    for (int k = t; k < CAT0; k += 256) {
        float a = (k < 256) ? x[b*256+k] : (k < 768) ? h[b*512 + (k-256)] : sh_r[k-768];
        s0 += a * W1[k*2];
        s1 += a * W1[k*2 + 1];
    }
    #pragma unroll
    for (int o = 16; o > 0; o >>= 1) {
        s0 += __shfl_xor_sync(0xffffffffu, s0, o);
        s1 += __shfl_xor_sync(0xffffffffu, s1, o);
    }
    if (lane == 0) { redp[w] = s0; redq[w] = s1; }
    __syncthreads();
    if (t == 0) {
        float a0 = 0.f, a1 = 0.f;
        #pragma unroll
        for (int j = 0; j < 8; j++) { a0 += redp[j]; a1 += redq[j]; }
        const float ST = (float)(10.0/3.0);
        g_ab[b*2]     = sigm((a0 + b1[0] + gumbel(nsig[b*2]))   * ST);
        g_ab[b*2 + 1] = sigm((a1 + b1[1] + gumbel(nsig[b*2+1])) * ST);
    }
}

// ---------------- launch ----------------
extern "C" void kernel_launch(void* const* d_in, const int* in_sizes, int n_in,
                              void* d_out, int out_size) {
    const float* x        = (const float*)d_in[0];
    const float* h        = (const float*)d_in[1];
    const float* c        = (const float*)d_in[2];
    const float* hmem     = (const float*)d_in[3];
    const float* u_t      = (const float*)d_in[4];
    const float* prev     = (const float*)d_in[5];
    const float* W_full   = (const float*)d_in[6];
    const float* bias     = (const float*)d_in[7];
    const float* W_full1  = (const float*)d_in[8];
    const float* bias1    = (const float*)d_in[9];
    const float* W_full2  = (const float*)d_in[10];
    const float* bias2    = (const float*)d_in[11];
    const float* keys     = (const float*)d_in[12];
    const float* vec_a    = (const float*)d_in[13];
    const float* W_fc     = (const float*)d_in[14];
    const float* b_fc     = (const float*)d_in[15];
    const float* W_fc1    = (const float*)d_in[16];
    const float* b_fc1    = (const float*)d_in[17];
    const float* noise_sm = (const float*)d_in[18];
    const float* noise_sig= (const float*)d_in[19];
    const int*   memcnt   = (const int*)d_in[20];

    float* out      = (float*)d_out;
    float* out_hmem = out + (size_t)BSZ * OC;

    float *pbase, *puinv;
    bf16 *pWbh;
    cudaGetSymbolAddress((void**)&pbase, g_base);
    cudaGetSymbolAddress((void**)&puinv, g_uinv);
    cudaGetSymbolAddress((void**)&pWbh,  g_Wb_hi);

    auto kBase = mgemm_base<2,4,1,2>;  // 32x64 tile, 1-pass
    cudaFuncSetAttribute((const void*)k_gp,  cudaFuncAttributeMaxDynamicSharedMemorySize, GP_SMEM);
    cudaFuncSetAttribute((const void*)kBase, cudaFuncAttributeMaxDynamicSharedMemorySize, 15360);
    cudaFuncSetAttribute((const void*)k_hw,  cudaFuncAttributeMaxDynamicSharedMemorySize, HW_SMEM);

    // 1. all prep
    k_prep<<<T_ALL, 256>>>(W_full, W_full2, W_fc, W_fc1, keys, vec_a, u_t);
    // 2. base = [x,c,u^]@Wb + b_fc
    kBase<<<dim3(2, BSZ/32), 256, 15360>>>(
        x, c, u_t, puinv, pWbh, pbase, b_fc, 128, XCU);
    // 3. hid + head + argmax + r + ab
    k_hid_mma<<<BSZ, 256>>>(hmem, prev, noise_sm, x, h, W_full1, bias1, noise_sig, out);
    // 4. merged G + P GEMM + interleaved hmem copy
    k_gp<<<dim3(GP_NGX + HS/64, BSZ/128), 256, GP_SMEM>>>(x, h, bias, bias2, hmem, out_hmem);
    // 5. h_w GEMM with fused LSTM epilogue (writes new_h to d_out) + hmem row scatter
    k_hw<<<dim3(1, BSZ/32), 128, HW_SMEM>>>(x, c, b_fc1, memcnt, out, out_hmem);
    (void)in_sizes; (void)n_in; (void)out_size;
}